// round 15
// baseline (speedup 1.0000x reference)
#include <cuda_runtime.h>
#include <cuda_bf16.h>
#include <cuda_fp16.h>
#include <cstdint>

#define Bc 4
#define Sc 4096
#define Dc 128
#define Kc 64
#define Vc 128
#define BSc (Bc*Sc)
#define OUTC 256

// ---------------- scratch ----------------
__device__ __half g_Qs[(size_t)BSc * 64];              // fp16 Q rows
__device__ __half g_Ks[(size_t)BSc * 64];              // fp16 K rows
__device__ float  g_Vp[(size_t)BSc * Vc];
__device__ __half g_E[(size_t)Bc * Sc * Sc];           // exp(scores), causal zeros
__device__ __half g_Vt[(size_t)Bc * Vc * Sc];          // [b][v][s], V/denom, fp16
__device__ float  g_denom[BSc];

// ---------------- PTX helpers ----------------
__device__ __forceinline__ uint32_t smem_u32(const void* p) {
    uint32_t a;
    asm("{ .reg .u64 t; cvta.to.shared.u64 t, %1; cvt.u32.u64 %0, t; }" : "=r"(a) : "l"(p));
    return a;
}
#define CP16(dst, src) \
    asm volatile("cp.async.cg.shared.global [%0], [%1], 16;" :: "r"(dst), "l"(src))
#define CP_COMMIT() asm volatile("cp.async.commit_group;" ::: "memory")
#define CP_WAITG(n) asm volatile("cp.async.wait_group %0;" :: "n"(n) : "memory")
#define LDM_X4(d0, d1, d2, d3, a) \
    asm volatile("ldmatrix.sync.aligned.m8n8.x4.shared.b16 {%0,%1,%2,%3}, [%4];" \
        : "=r"(d0), "=r"(d1), "=r"(d2), "=r"(d3) : "r"(a))

__device__ __forceinline__ void mma_bf16(float* d, const uint32_t* a, const uint32_t* b) {
    asm volatile("mma.sync.aligned.m16n8k16.row.col.f32.bf16.bf16.f32 "
        "{%0,%1,%2,%3}, {%4,%5,%6,%7}, {%8,%9}, {%0,%1,%2,%3};"
        : "+f"(d[0]), "+f"(d[1]), "+f"(d[2]), "+f"(d[3])
        : "r"(a[0]), "r"(a[1]), "r"(a[2]), "r"(a[3]), "r"(b[0]), "r"(b[1]));
}
__device__ __forceinline__ void mma_f16(float* d, const uint32_t* a, const uint32_t* b) {
    asm volatile("mma.sync.aligned.m16n8k16.row.col.f32.f16.f16.f32 "
        "{%0,%1,%2,%3}, {%4,%5,%6,%7}, {%8,%9}, {%0,%1,%2,%3};"
        : "+f"(d[0]), "+f"(d[1]), "+f"(d[2]), "+f"(d[3])
        : "r"(a[0]), "r"(a[1]), "r"(a[2]), "r"(a[3]), "r"(b[0]), "r"(b[1]));
}
// pack two fp32 -> bf16x2 in ONE cvt (v0 -> low half, v1 -> high half)
__device__ __forceinline__ uint32_t cvt2bf(float v0, float v1) {
    uint32_t r;
    asm("cvt.rn.bf16x2.f32 %0, %1, %2;" : "=r"(r) : "f"(v1), "f"(v0));
    return r;
}
__device__ __forceinline__ float bflo(uint32_t p) { return __uint_as_float(p << 16); }
__device__ __forceinline__ float bfhi(uint32_t p) { return __uint_as_float(p & 0xFFFF0000u); }
__device__ __forceinline__ uint32_t cvt2h(float v0, float v1) {
    __half2 t = __floats2half2_rn(v0, v1);
    return *reinterpret_cast<uint32_t*>(&t);
}

// exp(s/8) as 2^(s*C): ex2.approx.f16x2 + fp32 residual correction.
__device__ __forceinline__ uint32_t exp2h2(float t0, float t1) {
    __half2 th = __floats2half2_rn(t0, t1);
    uint32_t thu = *reinterpret_cast<uint32_t*>(&th);
    uint32_t eu;
    asm("ex2.approx.f16x2 %0, %1;" : "=r"(eu) : "r"(thu));
    float tl0 = t0 - __half2float(__low2half(th));
    float tl1 = t1 - __half2float(__high2half(th));
    __half2 c = __floats2half2_rn(fmaf(0.6931472f, tl0, 1.0f),
                                  fmaf(0.6931472f, tl1, 1.0f));
    __half2 e = *reinterpret_cast<__half2*>(&eu);
    e = __hmul2(e, c);
    return *reinterpret_cast<uint32_t*>(&e);
}

// causal (qt, group-of-8) decode, heaviest first; sum over qt of ceil((qt+1)/8) = 80
__device__ __forceinline__ void decode_qt(int bx, int& qt, int& g0, int& g1) {
    int lin = 79 - bx;
    int base = 0; qt = 0;
    for (;;) { int gq = (qt + 8) >> 3; if (lin < base + gq) break; base += gq; qt++; }
    g0 = (lin - base) * 8;
    g1 = min(qt + 1, g0 + 8);
}

// ---------------- kernel 1: projections (mma split-bf16) -------------------
#define PJ_A0 0
#define PJ_A1 34816
#define PJ_B0 69632
#define PJ_B1 104448
#define PJ_BIAS 139264
#define PJ_SMEM 139776

__global__ __launch_bounds__(256) void proj_kernel(
    const float* __restrict__ x,
    const float* __restrict__ Wq, const float* __restrict__ bq,
    const float* __restrict__ Wk, const float* __restrict__ bk,
    const float* __restrict__ Wv, const float* __restrict__ bv,
    float* __restrict__ out) {
    extern __shared__ char smem[];
    const uint32_t sb = smem_u32(smem);
    const int tid = threadIdx.x;
    const int wid = tid >> 5, lane = tid & 31;
    const int grp = lane >> 2, qr = lane & 3;
    const int wm = wid >> 1, wn = wid & 1;
    const int nh = blockIdx.y;
    const int t0 = blockIdx.x * 128;

    if (nh == 0) {
        int i = blockIdx.x * 256 + tid;
        if (i < BSc) g_denom[i] = 0.0f;
    }
    if (tid < 128) {
        float bvv = (nh == 0) ? ((tid < 64) ? bq[tid] : bk[tid - 64]) : bv[tid];
        ((float*)(smem + PJ_BIAS))[tid] = bvv;
    }

    #pragma unroll
    for (int i = 0; i < 16; i++) {
        int idx = tid + i * 256;
        int r = idx >> 5, c4 = idx & 31;
        int ch = c4 >> 4, cc = c4 & 15;
        float4 a = *(const float4*)&x[(size_t)(t0 + r) * 128 + c4 * 4];
        if (nh == 0) {   // fused concat: out[:, :128] = x, out[:, 128:] = 0
            ((float4*)out)[(size_t)(t0 + r) * 64 + c4] = a;
            ((float4*)out)[(size_t)(t0 + r) * 64 + 32 + c4] =
                make_float4(0.f, 0.f, 0.f, 0.f);
        }
        uint32_t h01 = cvt2bf(a.x, a.y), h23 = cvt2bf(a.z, a.w);
        uint2 hi = make_uint2(h01, h23);
        uint2 lo = make_uint2(cvt2bf(a.x - bflo(h01), a.y - bfhi(h01)),
                              cvt2bf(a.z - bflo(h23), a.w - bfhi(h23)));
        char* ab = smem + (ch ? PJ_A1 : PJ_A0) + r * 272 + cc * 8;
        *(uint2*)ab = hi;
        *(uint2*)(ab + 128) = lo;

        const float* wsrc = (nh == 0)
            ? ((r < 64) ? (Wq + (size_t)r * 128) : (Wk + (size_t)(r - 64) * 128))
            : (Wv + (size_t)r * 128);
        float4 w = *(const float4*)&wsrc[c4 * 4];
        uint32_t g01 = cvt2bf(w.x, w.y), g23 = cvt2bf(w.z, w.w);
        uint2 whi = make_uint2(g01, g23);
        uint2 wlo = make_uint2(cvt2bf(w.x - bflo(g01), w.y - bfhi(g01)),
                               cvt2bf(w.z - bflo(g23), w.w - bfhi(g23)));
        char* bb = smem + (ch ? PJ_B1 : PJ_B0) + r * 272 + cc * 8;
        *(uint2*)bb = whi;
        *(uint2*)(bb + 128) = wlo;
    }
    __syncthreads();

    float acc[2][8][4] = {};
    const uint32_t aBase = sb + PJ_A0 + (wm*32 + (lane & 15))*272 + (lane >> 4)*16;
    const uint32_t bBase = sb + PJ_B0 + (wn*64 + (lane & 15))*272 + (lane >> 4)*16;
    const int aT[3] = {0, 1, 0}, bT[3] = {0, 0, 1};

    #pragma unroll
    for (int ch = 0; ch < 2; ch++) {
        #pragma unroll
        for (int t = 0; t < 3; t++) {
            #pragma unroll
            for (int ks = 0; ks < 4; ks++) {
                const uint32_t aOff = (uint32_t)(ch*34816 + aT[t]*128 + ks*32);
                const uint32_t bOff = (uint32_t)(ch*34816 + bT[t]*128 + ks*32);
                uint32_t afr[2][4];
                #pragma unroll
                for (int ma = 0; ma < 2; ma++)
                    LDM_X4(afr[ma][0], afr[ma][1], afr[ma][2], afr[ma][3],
                           aBase + ma*16*272 + aOff);
                uint32_t bfr[8][2];
                #pragma unroll
                for (int ng = 0; ng < 4; ng++) {
                    uint32_t d0, d1, d2, d3;
                    LDM_X4(d0, d1, d2, d3, bBase + ng*16*272 + bOff);
                    bfr[2*ng][0]   = d0; bfr[2*ng][1]   = d2;
                    bfr[2*ng+1][0] = d1; bfr[2*ng+1][1] = d3;
                }
                #pragma unroll
                for (int ma = 0; ma < 2; ma++)
                    #pragma unroll
                    for (int na = 0; na < 8; na++)
                        mma_bf16(acc[ma][na], afr[ma], bfr[na]);
            }
        }
    }
    __syncthreads();

    float* stage = (float*)smem;                 // [128][136]
    const float* biasS = (const float*)(smem + PJ_BIAS);
    #pragma unroll
    for (int ma = 0; ma < 2; ma++) {
        const int r0 = wm*32 + ma*16 + grp;
        #pragma unroll
        for (int na = 0; na < 8; na++) {
            const int c0 = wn*64 + na*8 + qr*2;
            stage[r0*136 + c0]     = acc[ma][na][0] + biasS[c0];
            stage[r0*136 + c0 + 1] = acc[ma][na][1] + biasS[c0 + 1];
            stage[(r0+8)*136 + c0]     = acc[ma][na][2] + biasS[c0];
            stage[(r0+8)*136 + c0 + 1] = acc[ma][na][3] + biasS[c0 + 1];
        }
    }
    __syncthreads();

    const int r = tid >> 1, h = tid & 1;
    if (nh == 0) {
        // h=0 -> Q row, h=1 -> K row; full 64-half rows (8 x uint4)
        uint32_t hp[32];
        #pragma unroll
        for (int k = 0; k < 32; k++)
            hp[k] = cvt2h(stage[r*136 + h*64 + 2*k], stage[r*136 + h*64 + 2*k + 1]);
        __half* dstrow = (h == 0 ? g_Qs : g_Ks) + (size_t)(t0 + r) * 64;
        uint4* dh = (uint4*)dstrow;
        #pragma unroll
        for (int k = 0; k < 8; k++) dh[k] = ((uint4*)hp)[k];
    } else {
        #pragma unroll
        for (int k = 0; k < 16; k++) {
            float4 v = *(const float4*)&stage[r*136 + h*64 + 4*k];
            *(float4*)&g_Vp[(size_t)(t0 + r) * 128 + h*64 + 4*k] = v;
        }
    }
}

// ---------------- kernel 2: scores (fp16, 3-deep K pipeline) ---------------
// Q resident (18KB), K triple-buffered (3x18KB); smem 72KB, 2 CTAs/SM.
#define SCQ 0
#define SCKB(k) (18432 + (k)*18432)
#define SC_SMEM 73728

__global__ __launch_bounds__(256, 2) void scores_kernel() {
    extern __shared__ char smem[];
    const uint32_t sb = smem_u32(smem);
    const int tid = threadIdx.x;
    const int wid = tid >> 5, lane = tid & 31;
    const int grp = lane >> 2, qr = lane & 3;
    const int wm = wid >> 1, wn = wid & 1;
    const int b = blockIdx.y;

    int qt, g0, g1;
    decode_qt(blockIdx.x, qt, g0, g1);
    const int nk = g1 - g0;
    const int q0 = qt * 128;

    const char* Qsrc = (const char*)(g_Qs + (size_t)(b * Sc + q0) * 64);
    const char* Kbase = (const char*)(g_Ks + (size_t)b * Sc * 64);

    // prologue: group0 = Q + K[0]; group1 = K[1] (if any)
    for (int idx = tid; idx < 1024; idx += 256) {
        int r = idx >> 3, ch = idx & 7;
        CP16(sb + SCQ + r*144 + ch*16, Qsrc + r*128 + ch*16);
        CP16(sb + SCKB(0) + r*144 + ch*16, Kbase + (size_t)(g0*128 + r)*128 + ch*16);
    }
    CP_COMMIT();
    if (nk > 1) {
        const size_t joff = (size_t)((g0 + 1) * 128) * 128;
        for (int idx = tid; idx < 512; idx += 256) {
            int r = idx >> 3, ch = idx & 7;
            CP16(sb + SCKB(1) + r*144 + ch*16, Kbase + joff + r*128 + ch*16);
            CP16(sb + SCKB(1) + (r+64)*144 + ch*16, Kbase + joff + (size_t)(r+64)*128 + ch*16);
        }
        CP_COMMIT();
    }

    const uint32_t aBase = sb + SCQ + (wm*32 + (lane & 15))*144 + (lane >> 4)*16;
    const uint32_t lmRow = (uint32_t)((wn*64 + (lane & 15))*144 + (lane >> 4)*16);
    const float C = 0.18033688011112042f;   // 0.125 * log2(e)

    for (int i = 0; i < nk; i++) {
        const int rem = nk - 1 - i;
        if (rem >= 2) {
            const uint32_t nbuf = SCKB((i + 2) % 3);
            const size_t joff = (size_t)((g0 + i + 2) * 128) * 128;
            for (int idx = tid; idx < 1024; idx += 256) {
                int r = idx >> 3, ch = idx & 7;
                CP16(sb + nbuf + r*144 + ch*16, Kbase + joff + r*128 + ch*16);
            }
            CP_COMMIT();
            CP_WAITG(2);
        } else if (rem == 1) {
            CP_WAITG(1);
        } else {
            CP_WAITG(0);
        }
        __syncthreads();

        float acc[2][8][4] = {};
        const uint32_t bBase = sb + SCKB(i % 3) + lmRow;
        #pragma unroll
        for (int ks = 0; ks < 4; ks++) {
            const uint32_t kOff = (uint32_t)(ks * 32);
            uint32_t afr[2][4];
            #pragma unroll
            for (int ma = 0; ma < 2; ma++)
                LDM_X4(afr[ma][0], afr[ma][1], afr[ma][2], afr[ma][3],
                       aBase + ma*16*144 + kOff);
            uint32_t bfr[8][2];
            #pragma unroll
            for (int ng = 0; ng < 4; ng++) {
                uint32_t d0, d1, d2, d3;
                LDM_X4(d0, d1, d2, d3, bBase + ng*16*144 + kOff);
                bfr[2*ng][0]   = d0; bfr[2*ng][1]   = d2;
                bfr[2*ng+1][0] = d1; bfr[2*ng+1][1] = d3;
            }
            #pragma unroll
            for (int ma = 0; ma < 2; ma++)
                #pragma unroll
                for (int na = 0; na < 8; na++)
                    mma_f16(acc[ma][na], afr[ma], bfr[na]);
        }

        // epilogue: exp -> direct E store + in-register column sums
        const int j0 = (g0 + i) * 128;
        float cs0[8] = {}, cs1[8] = {};
        #pragma unroll
        for (int ma = 0; ma < 2; ma++) {
            const int r0 = wm*32 + ma*16 + grp;
            const int qlo = q0 + r0, qhi = qlo + 8;
            __half* row0 = g_E + (size_t)(b * Sc + q0 + r0) * Sc;
            __half* row1 = row0 + (size_t)8 * Sc;
            #pragma unroll
            for (int na = 0; na < 8; na++) {
                const int c0 = wn*64 + na*8 + qr*2;
                const int jc = j0 + c0;
                float t0 = (jc     <= qlo) ? acc[ma][na][0] * C : -1000.0f;
                float t1 = (jc + 1 <= qlo) ? acc[ma][na][1] * C : -1000.0f;
                float t2 = (jc     <= qhi) ? acc[ma][na][2] * C : -1000.0f;
                float t3 = (jc + 1 <= qhi) ? acc[ma][na][3] * C : -1000.0f;
                uint32_t u0 = exp2h2(t0, t1), u1 = exp2h2(t2, t3);
                *(uint32_t*)&row0[jc] = u0;
                *(uint32_t*)&row1[jc] = u1;
                __half2 e0 = *reinterpret_cast<__half2*>(&u0);
                __half2 e1 = *reinterpret_cast<__half2*>(&u1);
                cs0[na] += __low2float(e0)  + __low2float(e1);
                cs1[na] += __high2float(e0) + __high2float(e1);
            }
        }
        #pragma unroll
        for (int na = 0; na < 8; na++) {
            #pragma unroll
            for (int m = 4; m <= 16; m <<= 1) {
                cs0[na] += __shfl_xor_sync(0xFFFFFFFFu, cs0[na], m);
                cs1[na] += __shfl_xor_sync(0xFFFFFFFFu, cs1[na], m);
            }
        }
        if (grp == 0) {
            #pragma unroll
            for (int na = 0; na < 8; na++) {
                const int jc = j0 + wn*64 + na*8 + qr*2;
                atomicAdd(&g_denom[b * Sc + jc],     cs0[na]);
                atomicAdd(&g_denom[b * Sc + jc + 1], cs1[na]);
            }
        }
        __syncthreads();   // buffer (i%3) fully consumed before refill
    }
}

// ---------------- kernel 3: vprep ----------------
__global__ __launch_bounds__(256) void vprep_kernel() {
    __shared__ float tile[32][133];
    __shared__ float invs[32];
    const int b = blockIdx.y, s0 = blockIdx.x * 32, tid = threadIdx.x;
    if (tid < 32) invs[tid] = 1.0f / g_denom[b * Sc + s0 + tid];
    __syncthreads();
    #pragma unroll
    for (int i = 0; i < 16; i++) {
        int idx = tid + i * 256;
        int r = idx >> 7, c = idx & 127;
        tile[r][c] = g_Vp[(size_t)(b * Sc + s0 + r) * Vc + c] * invs[r];
    }
    __syncthreads();
    const int v = tid >> 1, h = tid & 1;
    uint32_t packs[8];
    #pragma unroll
    for (int k = 0; k < 8; k++)
        packs[k] = cvt2h(tile[h*16 + 2*k][v], tile[h*16 + 2*k + 1][v]);
    uint4* dst = (uint4*)(g_Vt + (size_t)(b * Vc + v) * Sc + s0 + h*16);
    dst[0] = ((uint4*)packs)[0];
    dst[1] = ((uint4*)packs)[1];
}

// ---------------- kernel 4: attn (64-col chunks, 3-deep pipeline) ----------
// buffer k: E at k*36864, V at k*36864+18432; 3 buffers = 108KB, 2 CTAs/SM.
#define ABUF(k) ((k)*36864)
#define AT_SMEM 110592

__global__ __launch_bounds__(256, 2) void attn_kernel(float* __restrict__ out) {
    extern __shared__ char smem[];
    const uint32_t sb = smem_u32(smem);
    const int tid = threadIdx.x;
    const int wid = tid >> 5, lane = tid & 31;
    const int grp = lane >> 2, qr = lane & 3;
    const int wm = wid >> 1, wn = wid & 1;
    const int b = blockIdx.y;

    int qt, g0, g1;
    decode_qt(blockIdx.x, qt, g0, g1);
    const int nc = 2 * (g1 - g0);     // 64-col chunks
    const int c0base = 2 * g0;
    const int q0 = qt * 128;

    const char* Ebase = (const char*)g_E + (size_t)(b*Sc + q0) * Sc * 2;
    const char* Vbase = (const char*)g_Vt + (size_t)b * Vc * Sc * 2;

    // prologue: chunks 0 and 1
    #pragma unroll
    for (int p = 0; p < 2; p++) {
        if (p < nc) {
            const int jbyte = (c0base + p) * 128;
            const uint32_t eb = sb + ABUF(p), vb = eb + 18432;
            for (int idx = tid; idx < 1024; idx += 256) {
                int r = idx >> 3, ch = idx & 7;
                CP16(eb + r*144 + ch*16, Ebase + (size_t)r*Sc*2 + jbyte + ch*16);
                CP16(vb + r*144 + ch*16, Vbase + (size_t)r*Sc*2 + jbyte + ch*16);
            }
            CP_COMMIT();
        }
    }

    float acc[2][8][4] = {};
    const uint32_t lmA = (uint32_t)((wm*32 + (lane & 15))*144 + (lane >> 4)*16);
    const uint32_t lmB = (uint32_t)((wn*64 + (lane & 15))*144 + (lane >> 4)*16);

    for (int i = 0; i < nc; i++) {
        const int rem = nc - 1 - i;
        if (rem >= 2) {
            const uint32_t eb = sb + ABUF((i + 2) % 3), vb = eb + 18432;
            const int jbyte = (c0base + i + 2) * 128;
            for (int idx = tid; idx < 1024; idx += 256) {
                int r = idx >> 3, ch = idx & 7;
                CP16(eb + r*144 + ch*16, Ebase + (size_t)r*Sc*2 + jbyte + ch*16);
                CP16(vb + r*144 + ch*16, Vbase + (size_t)r*Sc*2 + jbyte + ch*16);
            }
            CP_COMMIT();
            CP_WAITG(2);
        } else if (rem == 1) {
            CP_WAITG(1);
        } else {
            CP_WAITG(0);
        }
        __syncthreads();

        const uint32_t aBase = sb + ABUF(i % 3) + lmA;
        const uint32_t bBase = sb + ABUF(i % 3) + 18432 + lmB;
        #pragma unroll
        for (int ks = 0; ks < 4; ks++) {
            const uint32_t kOff = (uint32_t)(ks * 32);
            uint32_t afr[2][4];
            #pragma unroll
            for (int ma = 0; ma < 2; ma++)
                LDM_X4(afr[ma][0], afr[ma][1], afr[ma][2], afr[ma][3],
                       aBase + ma*16*144 + kOff);
            uint32_t bfr[8][2];
            #pragma unroll
            for (int ng = 0; ng < 4; ng++) {
                uint32_t d0, d1, d2, d3;
                LDM_X4(d0, d1, d2, d3, bBase + ng*16*144 + kOff);
                bfr[2*ng][0]   = d0; bfr[2*ng][1]   = d2;
                bfr[2*ng+1][0] = d1; bfr[2*ng+1][1] = d3;
            }
            #pragma unroll
            for (int ma = 0; ma < 2; ma++)
                #pragma unroll
                for (int na = 0; na < 8; na++)
                    mma_f16(acc[ma][na], afr[ma], bfr[na]);
        }
        __syncthreads();
    }

    #pragma unroll
    for (int ma = 0; ma < 2; ma++) {
        const int r0 = q0 + wm*32 + ma*16 + grp;
        #pragma unroll
        for (int na = 0; na < 8; na++) {
            const int v0 = wn*64 + na*8 + qr*2;
            atomicAdd(&out[(size_t)(b*Sc + r0)*OUTC + Dc + v0],     acc[ma][na][0]);
            atomicAdd(&out[(size_t)(b*Sc + r0)*OUTC + Dc + v0 + 1], acc[ma][na][1]);
            atomicAdd(&out[(size_t)(b*Sc + r0 + 8)*OUTC + Dc + v0],     acc[ma][na][2]);
            atomicAdd(&out[(size_t)(b*Sc + r0 + 8)*OUTC + Dc + v0 + 1], acc[ma][na][3]);
        }
    }
}

// ---------------- launch ----------------
extern "C" void kernel_launch(void* const* d_in, const int* in_sizes, int n_in,
                              void* d_out, int out_size) {
    const float* x  = (const float*)d_in[0];
    const float* Wq = (const float*)d_in[1];
    const float* bq = (const float*)d_in[2];
    const float* Wk = (const float*)d_in[3];
    const float* bk = (const float*)d_in[4];
    const float* Wv = (const float*)d_in[5];
    const float* bv = (const float*)d_in[6];
    float* out = (float*)d_out;

    cudaFuncSetAttribute(proj_kernel,   cudaFuncAttributeMaxDynamicSharedMemorySize, PJ_SMEM);
    cudaFuncSetAttribute(scores_kernel, cudaFuncAttributeMaxDynamicSharedMemorySize, SC_SMEM);
    cudaFuncSetAttribute(attn_kernel,   cudaFuncAttributeMaxDynamicSharedMemorySize, AT_SMEM);

    proj_kernel<<<dim3(BSc / 128, 2), 256, PJ_SMEM>>>(x, Wq, bq, Wk, bk, Wv, bv, out);
    scores_kernel<<<dim3(80, Bc), 256, SC_SMEM>>>();
    vprep_kernel<<<dim3(Sc / 32, Bc), 256>>>();
    attn_kernel<<<dim3(80, Bc), 256, AT_SMEM>>>(out);
}

// round 16
// speedup vs baseline: 1.0796x; 1.0796x over previous
#include <cuda_runtime.h>
#include <cuda_bf16.h>
#include <cuda_fp16.h>
#include <cstdint>

#define Bc 4
#define Sc 4096
#define Dc 128
#define Kc 64
#define Vc 128
#define BSc (Bc*Sc)
#define OUTC 256

// ---------------- scratch ----------------
__device__ __half g_Qs[(size_t)BSc * 64];              // fp16 Q rows
__device__ __half g_Ks[(size_t)BSc * 64];              // fp16 K rows
__device__ float  g_Vp[(size_t)BSc * Vc];
__device__ __half g_E[(size_t)Bc * Sc * Sc];           // exp(scores), causal zeros
__device__ __half g_Vt[(size_t)Bc * Vc * Sc];          // [b][v][s], V/denom, fp16
__device__ float  g_denom[BSc];

// ---------------- PTX helpers ----------------
__device__ __forceinline__ uint32_t smem_u32(const void* p) {
    uint32_t a;
    asm("{ .reg .u64 t; cvta.to.shared.u64 t, %1; cvt.u32.u64 %0, t; }" : "=r"(a) : "l"(p));
    return a;
}
#define CP16(dst, src) \
    asm volatile("cp.async.cg.shared.global [%0], [%1], 16;" :: "r"(dst), "l"(src))
#define CP_COMMIT() asm volatile("cp.async.commit_group;" ::: "memory")
#define CP_WAITG(n) asm volatile("cp.async.wait_group %0;" :: "n"(n) : "memory")
#define LDM_X4(d0, d1, d2, d3, a) \
    asm volatile("ldmatrix.sync.aligned.m8n8.x4.shared.b16 {%0,%1,%2,%3}, [%4];" \
        : "=r"(d0), "=r"(d1), "=r"(d2), "=r"(d3) : "r"(a))

__device__ __forceinline__ void mma_f16(float* d, const uint32_t* a, const uint32_t* b) {
    asm volatile("mma.sync.aligned.m16n8k16.row.col.f32.f16.f16.f32 "
        "{%0,%1,%2,%3}, {%4,%5,%6,%7}, {%8,%9}, {%0,%1,%2,%3};"
        : "+f"(d[0]), "+f"(d[1]), "+f"(d[2]), "+f"(d[3])
        : "r"(a[0]), "r"(a[1]), "r"(a[2]), "r"(a[3]), "r"(b[0]), "r"(b[1]));
}
__device__ __forceinline__ uint32_t cvt2h(float v0, float v1) {
    __half2 t = __floats2half2_rn(v0, v1);
    return *reinterpret_cast<uint32_t*>(&t);
}

// exp(s/8) as 2^(s*C): ex2.approx.f16x2 + fp32 residual correction.
__device__ __forceinline__ uint32_t exp2h2(float t0, float t1) {
    __half2 th = __floats2half2_rn(t0, t1);
    uint32_t thu = *reinterpret_cast<uint32_t*>(&th);
    uint32_t eu;
    asm("ex2.approx.f16x2 %0, %1;" : "=r"(eu) : "r"(thu));
    float tl0 = t0 - __half2float(__low2half(th));
    float tl1 = t1 - __half2float(__high2half(th));
    __half2 c = __floats2half2_rn(fmaf(0.6931472f, tl0, 1.0f),
                                  fmaf(0.6931472f, tl1, 1.0f));
    __half2 e = *reinterpret_cast<__half2*>(&eu);
    e = __hmul2(e, c);
    return *reinterpret_cast<uint32_t*>(&e);
}

// causal (qt, group-of-8) decode, heaviest first; sum over qt of ceil((qt+1)/8) = 80
__device__ __forceinline__ void decode_qt(int bx, int& qt, int& g0, int& g1) {
    int lin = 79 - bx;
    int base = 0; qt = 0;
    for (;;) { int gq = (qt + 8) >> 3; if (lin < base + gq) break; base += gq; qt++; }
    g0 = (lin - base) * 8;
    g1 = min(qt + 1, g0 + 8);
}

// ---------------- kernel 1: projections (single fp16 mma) ------------------
// nh==0 -> [Q|K] (cols 0-63 / 64-127) + fused concat; nh==1 -> V.
#define PJ_A0 0
#define PJ_A1 18432
#define PJ_B0 36864
#define PJ_B1 55296
#define PJ_BIAS 73728
#define PJ_SMEM 74240

__global__ __launch_bounds__(256, 2) void proj_kernel(
    const float* __restrict__ x,
    const float* __restrict__ Wq, const float* __restrict__ bq,
    const float* __restrict__ Wk, const float* __restrict__ bk,
    const float* __restrict__ Wv, const float* __restrict__ bv,
    float* __restrict__ out) {
    extern __shared__ char smem[];
    const uint32_t sb = smem_u32(smem);
    const int tid = threadIdx.x;
    const int wid = tid >> 5, lane = tid & 31;
    const int grp = lane >> 2, qr = lane & 3;
    const int wm = wid >> 1, wn = wid & 1;
    const int nh = blockIdx.y;
    const int t0 = blockIdx.x * 128;

    if (nh == 0) {
        int i = blockIdx.x * 256 + tid;
        if (i < BSc) g_denom[i] = 0.0f;
    }
    if (tid < 128) {
        float bvv = (nh == 0) ? ((tid < 64) ? bq[tid] : bk[tid - 64]) : bv[tid];
        ((float*)(smem + PJ_BIAS))[tid] = bvv;
    }

    #pragma unroll
    for (int i = 0; i < 16; i++) {
        int idx = tid + i * 256;
        int r = idx >> 5, c4 = idx & 31;
        int ch = c4 >> 4, cc = c4 & 15;
        float4 a = *(const float4*)&x[(size_t)(t0 + r) * 128 + c4 * 4];
        if (nh == 0) {   // fused concat: out[:, :128] = x, out[:, 128:] = 0
            ((float4*)out)[(size_t)(t0 + r) * 64 + c4] = a;
            ((float4*)out)[(size_t)(t0 + r) * 64 + 32 + c4] =
                make_float4(0.f, 0.f, 0.f, 0.f);
        }
        *(uint2*)(smem + (ch ? PJ_A1 : PJ_A0) + r * 144 + cc * 8) =
            make_uint2(cvt2h(a.x, a.y), cvt2h(a.z, a.w));

        const float* wsrc = (nh == 0)
            ? ((r < 64) ? (Wq + (size_t)r * 128) : (Wk + (size_t)(r - 64) * 128))
            : (Wv + (size_t)r * 128);
        float4 w = *(const float4*)&wsrc[c4 * 4];
        *(uint2*)(smem + (ch ? PJ_B1 : PJ_B0) + r * 144 + cc * 8) =
            make_uint2(cvt2h(w.x, w.y), cvt2h(w.z, w.w));
    }
    __syncthreads();

    float acc[2][8][4] = {};
    const uint32_t aBase = sb + PJ_A0 + (wm*32 + (lane & 15))*144 + (lane >> 4)*16;
    const uint32_t bBase = sb + PJ_B0 + (wn*64 + (lane & 15))*144 + (lane >> 4)*16;

    #pragma unroll
    for (int ch = 0; ch < 2; ch++) {
        #pragma unroll
        for (int ks = 0; ks < 4; ks++) {
            const uint32_t off = (uint32_t)(ch*18432 + ks*32);
            uint32_t afr[2][4];
            #pragma unroll
            for (int ma = 0; ma < 2; ma++)
                LDM_X4(afr[ma][0], afr[ma][1], afr[ma][2], afr[ma][3],
                       aBase + ma*16*144 + off);
            uint32_t bfr[8][2];
            #pragma unroll
            for (int ng = 0; ng < 4; ng++) {
                uint32_t d0, d1, d2, d3;
                LDM_X4(d0, d1, d2, d3, bBase + ng*16*144 + off);
                bfr[2*ng][0]   = d0; bfr[2*ng][1]   = d2;
                bfr[2*ng+1][0] = d1; bfr[2*ng+1][1] = d3;
            }
            #pragma unroll
            for (int ma = 0; ma < 2; ma++)
                #pragma unroll
                for (int na = 0; na < 8; na++)
                    mma_f16(acc[ma][na], afr[ma], bfr[na]);
        }
    }
    __syncthreads();

    float* stage = (float*)smem;                 // [128][136] overlays dead tiles
    const float* biasS = (const float*)(smem + PJ_BIAS);
    #pragma unroll
    for (int ma = 0; ma < 2; ma++) {
        const int r0 = wm*32 + ma*16 + grp;
        #pragma unroll
        for (int na = 0; na < 8; na++) {
            const int c0 = wn*64 + na*8 + qr*2;
            stage[r0*136 + c0]     = acc[ma][na][0] + biasS[c0];
            stage[r0*136 + c0 + 1] = acc[ma][na][1] + biasS[c0 + 1];
            stage[(r0+8)*136 + c0]     = acc[ma][na][2] + biasS[c0];
            stage[(r0+8)*136 + c0 + 1] = acc[ma][na][3] + biasS[c0 + 1];
        }
    }
    __syncthreads();

    const int r = tid >> 1, h = tid & 1;
    if (nh == 0) {
        // h=0 -> Q row, h=1 -> K row; full 64-half rows (8 x uint4)
        uint32_t hp[32];
        #pragma unroll
        for (int k = 0; k < 32; k++)
            hp[k] = cvt2h(stage[r*136 + h*64 + 2*k], stage[r*136 + h*64 + 2*k + 1]);
        __half* dstrow = (h == 0 ? g_Qs : g_Ks) + (size_t)(t0 + r) * 64;
        uint4* dh = (uint4*)dstrow;
        #pragma unroll
        for (int k = 0; k < 8; k++) dh[k] = ((uint4*)hp)[k];
    } else {
        #pragma unroll
        for (int k = 0; k < 16; k++) {
            float4 v = *(const float4*)&stage[r*136 + h*64 + 4*k];
            *(float4*)&g_Vp[(size_t)(t0 + r) * 128 + h*64 + 4*k] = v;
        }
    }
}

// ---------------- kernel 2: scores (fp16, 3-deep K pipeline) ---------------
#define SCQ 0
#define SCKB(k) (18432 + (k)*18432)
#define SC_SMEM 73728

__global__ __launch_bounds__(256, 2) void scores_kernel() {
    extern __shared__ char smem[];
    const uint32_t sb = smem_u32(smem);
    const int tid = threadIdx.x;
    const int wid = tid >> 5, lane = tid & 31;
    const int grp = lane >> 2, qr = lane & 3;
    const int wm = wid >> 1, wn = wid & 1;
    const int b = blockIdx.y;

    int qt, g0, g1;
    decode_qt(blockIdx.x, qt, g0, g1);
    const int nk = g1 - g0;
    const int q0 = qt * 128;

    const char* Qsrc = (const char*)(g_Qs + (size_t)(b * Sc + q0) * 64);
    const char* Kbase = (const char*)(g_Ks + (size_t)b * Sc * 64);

    for (int idx = tid; idx < 1024; idx += 256) {
        int r = idx >> 3, ch = idx & 7;
        CP16(sb + SCQ + r*144 + ch*16, Qsrc + r*128 + ch*16);
        CP16(sb + SCKB(0) + r*144 + ch*16, Kbase + (size_t)(g0*128 + r)*128 + ch*16);
    }
    CP_COMMIT();
    if (nk > 1) {
        const size_t joff = (size_t)((g0 + 1) * 128) * 128;
        for (int idx = tid; idx < 512; idx += 256) {
            int r = idx >> 3, ch = idx & 7;
            CP16(sb + SCKB(1) + r*144 + ch*16, Kbase + joff + r*128 + ch*16);
            CP16(sb + SCKB(1) + (r+64)*144 + ch*16, Kbase + joff + (size_t)(r+64)*128 + ch*16);
        }
        CP_COMMIT();
    }

    const uint32_t aBase = sb + SCQ + (wm*32 + (lane & 15))*144 + (lane >> 4)*16;
    const uint32_t lmRow = (uint32_t)((wn*64 + (lane & 15))*144 + (lane >> 4)*16);
    const float C = 0.18033688011112042f;   // 0.125 * log2(e)

    for (int i = 0; i < nk; i++) {
        const int rem = nk - 1 - i;
        if (rem >= 2) {
            const uint32_t nbuf = SCKB((i + 2) % 3);
            const size_t joff = (size_t)((g0 + i + 2) * 128) * 128;
            for (int idx = tid; idx < 1024; idx += 256) {
                int r = idx >> 3, ch = idx & 7;
                CP16(sb + nbuf + r*144 + ch*16, Kbase + joff + r*128 + ch*16);
            }
            CP_COMMIT();
            CP_WAITG(2);
        } else if (rem == 1) {
            CP_WAITG(1);
        } else {
            CP_WAITG(0);
        }
        __syncthreads();

        float acc[2][8][4] = {};
        const uint32_t bBase = sb + SCKB(i % 3) + lmRow;
        #pragma unroll
        for (int ks = 0; ks < 4; ks++) {
            const uint32_t kOff = (uint32_t)(ks * 32);
            uint32_t afr[2][4];
            #pragma unroll
            for (int ma = 0; ma < 2; ma++)
                LDM_X4(afr[ma][0], afr[ma][1], afr[ma][2], afr[ma][3],
                       aBase + ma*16*144 + kOff);
            uint32_t bfr[8][2];
            #pragma unroll
            for (int ng = 0; ng < 4; ng++) {
                uint32_t d0, d1, d2, d3;
                LDM_X4(d0, d1, d2, d3, bBase + ng*16*144 + kOff);
                bfr[2*ng][0]   = d0; bfr[2*ng][1]   = d2;
                bfr[2*ng+1][0] = d1; bfr[2*ng+1][1] = d3;
            }
            #pragma unroll
            for (int ma = 0; ma < 2; ma++)
                #pragma unroll
                for (int na = 0; na < 8; na++)
                    mma_f16(acc[ma][na], afr[ma], bfr[na]);
        }

        const int j0 = (g0 + i) * 128;
        float cs0[8] = {}, cs1[8] = {};
        #pragma unroll
        for (int ma = 0; ma < 2; ma++) {
            const int r0 = wm*32 + ma*16 + grp;
            const int qlo = q0 + r0, qhi = qlo + 8;
            __half* row0 = g_E + (size_t)(b * Sc + q0 + r0) * Sc;
            __half* row1 = row0 + (size_t)8 * Sc;
            #pragma unroll
            for (int na = 0; na < 8; na++) {
                const int c0 = wn*64 + na*8 + qr*2;
                const int jc = j0 + c0;
                float t0 = (jc     <= qlo) ? acc[ma][na][0] * C : -1000.0f;
                float t1 = (jc + 1 <= qlo) ? acc[ma][na][1] * C : -1000.0f;
                float t2 = (jc     <= qhi) ? acc[ma][na][2] * C : -1000.0f;
                float t3 = (jc + 1 <= qhi) ? acc[ma][na][3] * C : -1000.0f;
                uint32_t u0 = exp2h2(t0, t1), u1 = exp2h2(t2, t3);
                *(uint32_t*)&row0[jc] = u0;
                *(uint32_t*)&row1[jc] = u1;
                __half2 e0 = *reinterpret_cast<__half2*>(&u0);
                __half2 e1 = *reinterpret_cast<__half2*>(&u1);
                cs0[na] += __low2float(e0)  + __low2float(e1);
                cs1[na] += __high2float(e0) + __high2float(e1);
            }
        }
        #pragma unroll
        for (int na = 0; na < 8; na++) {
            #pragma unroll
            for (int m = 4; m <= 16; m <<= 1) {
                cs0[na] += __shfl_xor_sync(0xFFFFFFFFu, cs0[na], m);
                cs1[na] += __shfl_xor_sync(0xFFFFFFFFu, cs1[na], m);
            }
        }
        if (grp == 0) {
            #pragma unroll
            for (int na = 0; na < 8; na++) {
                const int jc = j0 + wn*64 + na*8 + qr*2;
                atomicAdd(&g_denom[b * Sc + jc],     cs0[na]);
                atomicAdd(&g_denom[b * Sc + jc + 1], cs1[na]);
            }
        }
        __syncthreads();
    }
}

// ---------------- kernel 3: vprep ----------------
__global__ __launch_bounds__(256) void vprep_kernel() {
    __shared__ float tile[32][133];
    __shared__ float invs[32];
    const int b = blockIdx.y, s0 = blockIdx.x * 32, tid = threadIdx.x;
    if (tid < 32) invs[tid] = 1.0f / g_denom[b * Sc + s0 + tid];
    __syncthreads();
    #pragma unroll
    for (int i = 0; i < 16; i++) {
        int idx = tid + i * 256;
        int r = idx >> 7, c = idx & 127;
        tile[r][c] = g_Vp[(size_t)(b * Sc + s0 + r) * Vc + c] * invs[r];
    }
    __syncthreads();
    const int v = tid >> 1, h = tid & 1;
    uint32_t packs[8];
    #pragma unroll
    for (int k = 0; k < 8; k++)
        packs[k] = cvt2h(tile[h*16 + 2*k][v], tile[h*16 + 2*k + 1][v]);
    uint4* dst = (uint4*)(g_Vt + (size_t)(b * Vc + v) * Sc + s0 + h*16);
    dst[0] = ((uint4*)packs)[0];
    dst[1] = ((uint4*)packs)[1];
}

// ---------------- kernel 4: attn (64-col chunks, 3-deep pipeline) ----------
#define ABUF(k) ((k)*36864)
#define AT_SMEM 110592

__global__ __launch_bounds__(256, 2) void attn_kernel(float* __restrict__ out) {
    extern __shared__ char smem[];
    const uint32_t sb = smem_u32(smem);
    const int tid = threadIdx.x;
    const int wid = tid >> 5, lane = tid & 31;
    const int grp = lane >> 2, qr = lane & 3;
    const int wm = wid >> 1, wn = wid & 1;
    const int b = blockIdx.y;

    int qt, g0, g1;
    decode_qt(blockIdx.x, qt, g0, g1);
    const int nc = 2 * (g1 - g0);
    const int c0base = 2 * g0;
    const int q0 = qt * 128;

    const char* Ebase = (const char*)g_E + (size_t)(b*Sc + q0) * Sc * 2;
    const char* Vbase = (const char*)g_Vt + (size_t)b * Vc * Sc * 2;

    #pragma unroll
    for (int p = 0; p < 2; p++) {
        if (p < nc) {
            const int jbyte = (c0base + p) * 128;
            const uint32_t eb = sb + ABUF(p), vb = eb + 18432;
            for (int idx = tid; idx < 1024; idx += 256) {
                int r = idx >> 3, ch = idx & 7;
                CP16(eb + r*144 + ch*16, Ebase + (size_t)r*Sc*2 + jbyte + ch*16);
                CP16(vb + r*144 + ch*16, Vbase + (size_t)r*Sc*2 + jbyte + ch*16);
            }
            CP_COMMIT();
        }
    }

    float acc[2][8][4] = {};
    const uint32_t lmA = (uint32_t)((wm*32 + (lane & 15))*144 + (lane >> 4)*16);
    const uint32_t lmB = (uint32_t)((wn*64 + (lane & 15))*144 + (lane >> 4)*16);

    for (int i = 0; i < nc; i++) {
        const int rem = nc - 1 - i;
        if (rem >= 2) {
            const uint32_t eb = sb + ABUF((i + 2) % 3), vb = eb + 18432;
            const int jbyte = (c0base + i + 2) * 128;
            for (int idx = tid; idx < 1024; idx += 256) {
                int r = idx >> 3, ch = idx & 7;
                CP16(eb + r*144 + ch*16, Ebase + (size_t)r*Sc*2 + jbyte + ch*16);
                CP16(vb + r*144 + ch*16, Vbase + (size_t)r*Sc*2 + jbyte + ch*16);
            }
            CP_COMMIT();
            CP_WAITG(2);
        } else if (rem == 1) {
            CP_WAITG(1);
        } else {
            CP_WAITG(0);
        }
        __syncthreads();

        const uint32_t aBase = sb + ABUF(i % 3) + lmA;
        const uint32_t bBase = sb + ABUF(i % 3) + 18432 + lmB;
        #pragma unroll
        for (int ks = 0; ks < 4; ks++) {
            const uint32_t kOff = (uint32_t)(ks * 32);
            uint32_t afr[2][4];
            #pragma unroll
            for (int ma = 0; ma < 2; ma++)
                LDM_X4(afr[ma][0], afr[ma][1], afr[ma][2], afr[ma][3],
                       aBase + ma*16*144 + kOff);
            uint32_t bfr[8][2];
            #pragma unroll
            for (int ng = 0; ng < 4; ng++) {
                uint32_t d0, d1, d2, d3;
                LDM_X4(d0, d1, d2, d3, bBase + ng*16*144 + kOff);
                bfr[2*ng][0]   = d0; bfr[2*ng][1]   = d2;
                bfr[2*ng+1][0] = d1; bfr[2*ng+1][1] = d3;
            }
            #pragma unroll
            for (int ma = 0; ma < 2; ma++)
                #pragma unroll
                for (int na = 0; na < 8; na++)
                    mma_f16(acc[ma][na], afr[ma], bfr[na]);
        }
        __syncthreads();
    }

    #pragma unroll
    for (int ma = 0; ma < 2; ma++) {
        const int r0 = q0 + wm*32 + ma*16 + grp;
        #pragma unroll
        for (int na = 0; na < 8; na++) {
            const int v0 = wn*64 + na*8 + qr*2;
            atomicAdd(&out[(size_t)(b*Sc + r0)*OUTC + Dc + v0],     acc[ma][na][0]);
            atomicAdd(&out[(size_t)(b*Sc + r0)*OUTC + Dc + v0 + 1], acc[ma][na][1]);
            atomicAdd(&out[(size_t)(b*Sc + r0 + 8)*OUTC + Dc + v0],     acc[ma][na][2]);
            atomicAdd(&out[(size_t)(b*Sc + r0 + 8)*OUTC + Dc + v0 + 1], acc[ma][na][3]);
        }
    }
}

// ---------------- launch ----------------
extern "C" void kernel_launch(void* const* d_in, const int* in_sizes, int n_in,
                              void* d_out, int out_size) {
    const float* x  = (const float*)d_in[0];
    const float* Wq = (const float*)d_in[1];
    const float* bq = (const float*)d_in[2];
    const float* Wk = (const float*)d_in[3];
    const float* bk = (const float*)d_in[4];
    const float* Wv = (const float*)d_in[5];
    const float* bv = (const float*)d_in[6];
    float* out = (float*)d_out;

    cudaFuncSetAttribute(proj_kernel,   cudaFuncAttributeMaxDynamicSharedMemorySize, PJ_SMEM);
    cudaFuncSetAttribute(scores_kernel, cudaFuncAttributeMaxDynamicSharedMemorySize, SC_SMEM);
    cudaFuncSetAttribute(attn_kernel,   cudaFuncAttributeMaxDynamicSharedMemorySize, AT_SMEM);

    proj_kernel<<<dim3(BSc / 128, 2), 256, PJ_SMEM>>>(x, Wq, bq, Wk, bk, Wv, bv, out);
    scores_kernel<<<dim3(80, Bc), 256, SC_SMEM>>>();
    vprep_kernel<<<dim3(Sc / 32, Bc), 256>>>();
    attn_kernel<<<dim3(80, Bc), 256, AT_SMEM>>>(out);
}

// round 17
// speedup vs baseline: 1.1878x; 1.1003x over previous
#include <cuda_runtime.h>
#include <cuda_bf16.h>
#include <cuda_fp16.h>
#include <cstdint>

#define Bc 4
#define Sc 4096
#define Dc 128
#define Kc 64
#define Vc 128
#define BSc (Bc*Sc)
#define OUTC 256

// ---------------- scratch ----------------
__device__ __half g_Qs[(size_t)BSc * 64];              // fp16 Q rows
__device__ __half g_Ks[(size_t)BSc * 64];              // fp16 K rows
__device__ float  g_Vp[(size_t)BSc * Vc];
__device__ __half g_E[(size_t)Bc * Sc * Sc];           // exp(scores), j-permuted per 64-block
__device__ __half g_Vt[(size_t)Bc * Vc * Sc];          // [b][v][s], s-permuted identically
__device__ float  g_denom[BSc];

// ---------------- PTX helpers ----------------
__device__ __forceinline__ uint32_t smem_u32(const void* p) {
    uint32_t a;
    asm("{ .reg .u64 t; cvta.to.shared.u64 t, %1; cvt.u32.u64 %0, t; }" : "=r"(a) : "l"(p));
    return a;
}
#define CP16(dst, src) \
    asm volatile("cp.async.cg.shared.global [%0], [%1], 16;" :: "r"(dst), "l"(src))
#define CP_COMMIT() asm volatile("cp.async.commit_group;" ::: "memory")
#define CP_WAITG(n) asm volatile("cp.async.wait_group %0;" :: "n"(n) : "memory")
#define LDM_X4(d0, d1, d2, d3, a) \
    asm volatile("ldmatrix.sync.aligned.m8n8.x4.shared.b16 {%0,%1,%2,%3}, [%4];" \
        : "=r"(d0), "=r"(d1), "=r"(d2), "=r"(d3) : "r"(a))

__device__ __forceinline__ void mma_f16(float* d, const uint32_t* a, const uint32_t* b) {
    asm volatile("mma.sync.aligned.m16n8k16.row.col.f32.f16.f16.f32 "
        "{%0,%1,%2,%3}, {%4,%5,%6,%7}, {%8,%9}, {%0,%1,%2,%3};"
        : "+f"(d[0]), "+f"(d[1]), "+f"(d[2]), "+f"(d[3])
        : "r"(a[0]), "r"(a[1]), "r"(a[2]), "r"(a[3]), "r"(b[0]), "r"(b[1]));
}
__device__ __forceinline__ uint32_t cvt2h(float v0, float v1) {
    __half2 t = __floats2half2_rn(v0, v1);
    return *reinterpret_cast<uint32_t*>(&t);
}

// exp(s/8) as 2^(s*C): raw ex2.approx.f16x2 (correction dropped; error ~7e-4/elt,
// norm-attenuated ~10x end-to-end).
__device__ __forceinline__ uint32_t exp2h2(float t0, float t1) {
    __half2 th = __floats2half2_rn(t0, t1);
    uint32_t thu = *reinterpret_cast<uint32_t*>(&th);
    uint32_t eu;
    asm("ex2.approx.f16x2 %0, %1;" : "=r"(eu) : "r"(thu));
    return eu;
}

// causal (qt, group-of-8) decode, heaviest first; sum over qt of ceil((qt+1)/8) = 80
__device__ __forceinline__ void decode_qt(int bx, int& qt, int& g0, int& g1) {
    int lin = 79 - bx;
    int base = 0; qt = 0;
    for (;;) { int gq = (qt + 8) >> 3; if (lin < base + gq) break; base += gq; qt++; }
    g0 = (lin - base) * 8;
    g1 = min(qt + 1, g0 + 8);
}

// ---------------- kernel 1: projections (single fp16 mma) ------------------
#define PJ_A0 0
#define PJ_A1 18432
#define PJ_B0 36864
#define PJ_B1 55296
#define PJ_BIAS 73728
#define PJ_SMEM 74240

__global__ __launch_bounds__(256, 2) void proj_kernel(
    const float* __restrict__ x,
    const float* __restrict__ Wq, const float* __restrict__ bq,
    const float* __restrict__ Wk, const float* __restrict__ bk,
    const float* __restrict__ Wv, const float* __restrict__ bv,
    float* __restrict__ out) {
    extern __shared__ char smem[];
    const uint32_t sb = smem_u32(smem);
    const int tid = threadIdx.x;
    const int wid = tid >> 5, lane = tid & 31;
    const int grp = lane >> 2, qr = lane & 3;
    const int wm = wid >> 1, wn = wid & 1;
    const int nh = blockIdx.y;
    const int t0 = blockIdx.x * 128;

    if (nh == 0) {
        int i = blockIdx.x * 256 + tid;
        if (i < BSc) g_denom[i] = 0.0f;
    }
    if (tid < 128) {
        float bvv = (nh == 0) ? ((tid < 64) ? bq[tid] : bk[tid - 64]) : bv[tid];
        ((float*)(smem + PJ_BIAS))[tid] = bvv;
    }

    #pragma unroll
    for (int i = 0; i < 16; i++) {
        int idx = tid + i * 256;
        int r = idx >> 5, c4 = idx & 31;
        int ch = c4 >> 4, cc = c4 & 15;
        float4 a = *(const float4*)&x[(size_t)(t0 + r) * 128 + c4 * 4];
        if (nh == 0) {   // fused concat
            ((float4*)out)[(size_t)(t0 + r) * 64 + c4] = a;
            ((float4*)out)[(size_t)(t0 + r) * 64 + 32 + c4] =
                make_float4(0.f, 0.f, 0.f, 0.f);
        }
        *(uint2*)(smem + (ch ? PJ_A1 : PJ_A0) + r * 144 + cc * 8) =
            make_uint2(cvt2h(a.x, a.y), cvt2h(a.z, a.w));

        const float* wsrc = (nh == 0)
            ? ((r < 64) ? (Wq + (size_t)r * 128) : (Wk + (size_t)(r - 64) * 128))
            : (Wv + (size_t)r * 128);
        float4 w = *(const float4*)&wsrc[c4 * 4];
        *(uint2*)(smem + (ch ? PJ_B1 : PJ_B0) + r * 144 + cc * 8) =
            make_uint2(cvt2h(w.x, w.y), cvt2h(w.z, w.w));
    }
    __syncthreads();

    float acc[2][8][4] = {};
    const uint32_t aBase = sb + PJ_A0 + (wm*32 + (lane & 15))*144 + (lane >> 4)*16;
    const uint32_t bBase = sb + PJ_B0 + (wn*64 + (lane & 15))*144 + (lane >> 4)*16;

    #pragma unroll
    for (int ch = 0; ch < 2; ch++) {
        #pragma unroll
        for (int ks = 0; ks < 4; ks++) {
            const uint32_t off = (uint32_t)(ch*18432 + ks*32);
            uint32_t afr[2][4];
            #pragma unroll
            for (int ma = 0; ma < 2; ma++)
                LDM_X4(afr[ma][0], afr[ma][1], afr[ma][2], afr[ma][3],
                       aBase + ma*16*144 + off);
            uint32_t bfr[8][2];
            #pragma unroll
            for (int ng = 0; ng < 4; ng++) {
                uint32_t d0, d1, d2, d3;
                LDM_X4(d0, d1, d2, d3, bBase + ng*16*144 + off);
                bfr[2*ng][0]   = d0; bfr[2*ng][1]   = d2;
                bfr[2*ng+1][0] = d1; bfr[2*ng+1][1] = d3;
            }
            #pragma unroll
            for (int ma = 0; ma < 2; ma++)
                #pragma unroll
                for (int na = 0; na < 8; na++)
                    mma_f16(acc[ma][na], afr[ma], bfr[na]);
        }
    }
    __syncthreads();

    float* stage = (float*)smem;                 // [128][136]
    const float* biasS = (const float*)(smem + PJ_BIAS);
    #pragma unroll
    for (int ma = 0; ma < 2; ma++) {
        const int r0 = wm*32 + ma*16 + grp;
        #pragma unroll
        for (int na = 0; na < 8; na++) {
            const int c0 = wn*64 + na*8 + qr*2;
            stage[r0*136 + c0]     = acc[ma][na][0] + biasS[c0];
            stage[r0*136 + c0 + 1] = acc[ma][na][1] + biasS[c0 + 1];
            stage[(r0+8)*136 + c0]     = acc[ma][na][2] + biasS[c0];
            stage[(r0+8)*136 + c0 + 1] = acc[ma][na][3] + biasS[c0 + 1];
        }
    }
    __syncthreads();

    const int r = tid >> 1, h = tid & 1;
    if (nh == 0) {
        uint32_t hp[32];
        #pragma unroll
        for (int k = 0; k < 32; k++)
            hp[k] = cvt2h(stage[r*136 + h*64 + 2*k], stage[r*136 + h*64 + 2*k + 1]);
        __half* dstrow = (h == 0 ? g_Qs : g_Ks) + (size_t)(t0 + r) * 64;
        uint4* dh = (uint4*)dstrow;
        #pragma unroll
        for (int k = 0; k < 8; k++) dh[k] = ((uint4*)hp)[k];
    } else {
        #pragma unroll
        for (int k = 0; k < 16; k++) {
            float4 v = *(const float4*)&stage[r*136 + h*64 + 4*k];
            *(float4*)&g_Vp[(size_t)(t0 + r) * 128 + h*64 + 4*k] = v;
        }
    }
}

// ---------------- kernel 2: scores (fp16, permuted coalesced E store) ------
#define SCQ 0
#define SCKB(k) (18432 + (k)*18432)
#define SC_SMEM 73728

__global__ __launch_bounds__(256, 2) void scores_kernel() {
    extern __shared__ char smem[];
    const uint32_t sb = smem_u32(smem);
    const int tid = threadIdx.x;
    const int wid = tid >> 5, lane = tid & 31;
    const int grp = lane >> 2, qr = lane & 3;
    const int wm = wid >> 1, wn = wid & 1;
    const int b = blockIdx.y;

    int qt, g0, g1;
    decode_qt(blockIdx.x, qt, g0, g1);
    const int nk = g1 - g0;
    const int q0 = qt * 128;

    const char* Qsrc = (const char*)(g_Qs + (size_t)(b * Sc + q0) * 64);
    const char* Kbase = (const char*)(g_Ks + (size_t)b * Sc * 64);

    for (int idx = tid; idx < 1024; idx += 256) {
        int r = idx >> 3, ch = idx & 7;
        CP16(sb + SCQ + r*144 + ch*16, Qsrc + r*128 + ch*16);
        CP16(sb + SCKB(0) + r*144 + ch*16, Kbase + (size_t)(g0*128 + r)*128 + ch*16);
    }
    CP_COMMIT();
    if (nk > 1) {
        const size_t joff = (size_t)((g0 + 1) * 128) * 128;
        for (int idx = tid; idx < 512; idx += 256) {
            int r = idx >> 3, ch = idx & 7;
            CP16(sb + SCKB(1) + r*144 + ch*16, Kbase + joff + r*128 + ch*16);
            CP16(sb + SCKB(1) + (r+64)*144 + ch*16, Kbase + joff + (size_t)(r+64)*128 + ch*16);
        }
        CP_COMMIT();
    }

    const uint32_t aBase = sb + SCQ + (wm*32 + (lane & 15))*144 + (lane >> 4)*16;
    const uint32_t lmRow = (uint32_t)((wn*64 + (lane & 15))*144 + (lane >> 4)*16);
    const float C = 0.18033688011112042f;   // 0.125 * log2(e)

    for (int i = 0; i < nk; i++) {
        const int rem = nk - 1 - i;
        if (rem >= 2) {
            const uint32_t nbuf = SCKB((i + 2) % 3);
            const size_t joff = (size_t)((g0 + i + 2) * 128) * 128;
            for (int idx = tid; idx < 1024; idx += 256) {
                int r = idx >> 3, ch = idx & 7;
                CP16(sb + nbuf + r*144 + ch*16, Kbase + joff + r*128 + ch*16);
            }
            CP_COMMIT();
            CP_WAITG(2);
        } else if (rem == 1) {
            CP_WAITG(1);
        } else {
            CP_WAITG(0);
        }
        __syncthreads();

        float acc[2][8][4] = {};
        const uint32_t bBase = sb + SCKB(i % 3) + lmRow;
        #pragma unroll
        for (int ks = 0; ks < 4; ks++) {
            const uint32_t kOff = (uint32_t)(ks * 32);
            uint32_t afr[2][4];
            #pragma unroll
            for (int ma = 0; ma < 2; ma++)
                LDM_X4(afr[ma][0], afr[ma][1], afr[ma][2], afr[ma][3],
                       aBase + ma*16*144 + kOff);
            uint32_t bfr[8][2];
            #pragma unroll
            for (int ng = 0; ng < 4; ng++) {
                uint32_t d0, d1, d2, d3;
                LDM_X4(d0, d1, d2, d3, bBase + ng*16*144 + kOff);
                bfr[2*ng][0]   = d0; bfr[2*ng][1]   = d2;
                bfr[2*ng+1][0] = d1; bfr[2*ng+1][1] = d3;
            }
            #pragma unroll
            for (int ma = 0; ma < 2; ma++)
                #pragma unroll
                for (int na = 0; na < 8; na++)
                    mma_f16(acc[ma][na], afr[ma], bfr[na]);
        }

        // epilogue: exp -> permuted coalesced E store + register column sums.
        // perm(j): j = na*8 + qr*2 + t  ->  p = (na>=4)*32 + qr*8 + (na&3)*2 + t
        // Lane's U0[0..3] = halfs qr*8+0..7 (16B), U0[4..7] = halfs 32+qr*8+0..7.
        const int j0 = (g0 + i) * 128;
        float cs0[8] = {}, cs1[8] = {};
        #pragma unroll
        for (int ma = 0; ma < 2; ma++) {
            const int r0 = wm*32 + ma*16 + grp;
            const int qlo = q0 + r0, qhi = qlo + 8;
            uint32_t U0[8], U1[8];
            #pragma unroll
            for (int na = 0; na < 8; na++) {
                const int jc = j0 + wn*64 + na*8 + qr*2;   // true j (mask/denom)
                float t0 = (jc     <= qlo) ? acc[ma][na][0] * C : -1000.0f;
                float t1 = (jc + 1 <= qlo) ? acc[ma][na][1] * C : -1000.0f;
                float t2 = (jc     <= qhi) ? acc[ma][na][2] * C : -1000.0f;
                float t3 = (jc + 1 <= qhi) ? acc[ma][na][3] * C : -1000.0f;
                U0[na] = exp2h2(t0, t1);
                U1[na] = exp2h2(t2, t3);
                __half2 e0 = *reinterpret_cast<__half2*>(&U0[na]);
                __half2 e1 = *reinterpret_cast<__half2*>(&U1[na]);
                cs0[na] += __low2float(e0)  + __low2float(e1);
                cs1[na] += __high2float(e0) + __high2float(e1);
            }
            char* base0 = (char*)(g_E + (size_t)(b*Sc + q0 + r0) * Sc + j0 + wn*64) + qr*16;
            char* base1 = base0 + (size_t)8 * Sc * 2;
            *(uint4*)(base0)      = make_uint4(U0[0], U0[1], U0[2], U0[3]);
            *(uint4*)(base0 + 64) = make_uint4(U0[4], U0[5], U0[6], U0[7]);
            *(uint4*)(base1)      = make_uint4(U1[0], U1[1], U1[2], U1[3]);
            *(uint4*)(base1 + 64) = make_uint4(U1[4], U1[5], U1[6], U1[7]);
        }
        #pragma unroll
        for (int na = 0; na < 8; na++) {
            #pragma unroll
            for (int m = 4; m <= 16; m <<= 1) {
                cs0[na] += __shfl_xor_sync(0xFFFFFFFFu, cs0[na], m);
                cs1[na] += __shfl_xor_sync(0xFFFFFFFFu, cs1[na], m);
            }
        }
        if (grp == 0) {
            #pragma unroll
            for (int na = 0; na < 8; na++) {
                const int jc = j0 + wn*64 + na*8 + qr*2;
                atomicAdd(&g_denom[b * Sc + jc],     cs0[na]);
                atomicAdd(&g_denom[b * Sc + jc + 1], cs1[na]);
            }
        }
        __syncthreads();
    }
}

// ---------------- kernel 3: vprep (inverse-permuted Vt) --------------------
// Vt[b][v][s0 + p] = V[s0 + invperm(p)][v] / denom,  per 64-block.
// invperm(p): blk=p>>5, qr=(p>>3)&3, na=blk*4+((p>>1)&3), t=p&1 -> j=na*8+qr*2+t
__global__ __launch_bounds__(256) void vprep_kernel() {
    __shared__ float tile[64][129];
    __shared__ float invs[64];
    const int b = blockIdx.y, s0 = blockIdx.x * 64, tid = threadIdx.x;
    if (tid < 64) invs[tid] = 1.0f / g_denom[b * Sc + s0 + tid];
    __syncthreads();
    #pragma unroll
    for (int i = 0; i < 32; i++) {
        int idx = tid + i * 256;
        int r = idx >> 7, c = idx & 127;
        tile[r][c] = g_Vp[(size_t)(b * Sc + s0 + r) * Vc + c] * invs[r];
    }
    __syncthreads();
    const int v = tid >> 1, h = tid & 1;    // h = perm block (p>>5)
    uint32_t packs[16];
    #pragma unroll
    for (int k = 0; k < 16; k++) {
        // p = h*32 + 2k -> j = (h*4 + (k&3))*8 + (k>>2)*2
        const int j = (h*4 + (k & 3)) * 8 + (k >> 2) * 2;
        packs[k] = cvt2h(tile[j][v], tile[j + 1][v]);
    }
    uint4* dst = (uint4*)(g_Vt + (size_t)(b * Vc + v) * Sc + s0 + h*32);
    #pragma unroll
    for (int k = 0; k < 4; k++) dst[k] = ((uint4*)packs)[k];
}

// ---------------- kernel 4: attn (64-col chunks, 3-deep pipeline) ----------
#define ABUF(k) ((k)*36864)
#define AT_SMEM 110592

__global__ __launch_bounds__(256, 2) void attn_kernel(float* __restrict__ out) {
    extern __shared__ char smem[];
    const uint32_t sb = smem_u32(smem);
    const int tid = threadIdx.x;
    const int wid = tid >> 5, lane = tid & 31;
    const int grp = lane >> 2, qr = lane & 3;
    const int wm = wid >> 1, wn = wid & 1;
    const int b = blockIdx.y;

    int qt, g0, g1;
    decode_qt(blockIdx.x, qt, g0, g1);
    const int nc = 2 * (g1 - g0);
    const int c0base = 2 * g0;
    const int q0 = qt * 128;

    const char* Ebase = (const char*)g_E + (size_t)(b*Sc + q0) * Sc * 2;
    const char* Vbase = (const char*)g_Vt + (size_t)b * Vc * Sc * 2;

    #pragma unroll
    for (int p = 0; p < 2; p++) {
        if (p < nc) {
            const int jbyte = (c0base + p) * 128;
            const uint32_t eb = sb + ABUF(p), vb = eb + 18432;
            for (int idx = tid; idx < 1024; idx += 256) {
                int r = idx >> 3, ch = idx & 7;
                CP16(eb + r*144 + ch*16, Ebase + (size_t)r*Sc*2 + jbyte + ch*16);
                CP16(vb + r*144 + ch*16, Vbase + (size_t)r*Sc*2 + jbyte + ch*16);
            }
            CP_COMMIT();
        }
    }

    float acc[2][8][4] = {};
    const uint32_t lmA = (uint32_t)((wm*32 + (lane & 15))*144 + (lane >> 4)*16);
    const uint32_t lmB = (uint32_t)((wn*64 + (lane & 15))*144 + (lane >> 4)*16);

    for (int i = 0; i < nc; i++) {
        const int rem = nc - 1 - i;
        if (rem >= 2) {
            const uint32_t eb = sb + ABUF((i + 2) % 3), vb = eb + 18432;
            const int jbyte = (c0base + i + 2) * 128;
            for (int idx = tid; idx < 1024; idx += 256) {
                int r = idx >> 3, ch = idx & 7;
                CP16(eb + r*144 + ch*16, Ebase + (size_t)r*Sc*2 + jbyte + ch*16);
                CP16(vb + r*144 + ch*16, Vbase + (size_t)r*Sc*2 + jbyte + ch*16);
            }
            CP_COMMIT();
            CP_WAITG(2);
        } else if (rem == 1) {
            CP_WAITG(1);
        } else {
            CP_WAITG(0);
        }
        __syncthreads();

        const uint32_t aBase = sb + ABUF(i % 3) + lmA;
        const uint32_t bBase = sb + ABUF(i % 3) + 18432 + lmB;
        #pragma unroll
        for (int ks = 0; ks < 4; ks++) {
            const uint32_t kOff = (uint32_t)(ks * 32);
            uint32_t afr[2][4];
            #pragma unroll
            for (int ma = 0; ma < 2; ma++)
                LDM_X4(afr[ma][0], afr[ma][1], afr[ma][2], afr[ma][3],
                       aBase + ma*16*144 + kOff);
            uint32_t bfr[8][2];
            #pragma unroll
            for (int ng = 0; ng < 4; ng++) {
                uint32_t d0, d1, d2, d3;
                LDM_X4(d0, d1, d2, d3, bBase + ng*16*144 + kOff);
                bfr[2*ng][0]   = d0; bfr[2*ng][1]   = d2;
                bfr[2*ng+1][0] = d1; bfr[2*ng+1][1] = d3;
            }
            #pragma unroll
            for (int ma = 0; ma < 2; ma++)
                #pragma unroll
                for (int na = 0; na < 8; na++)
                    mma_f16(acc[ma][na], afr[ma], bfr[na]);
        }
        __syncthreads();
    }

    #pragma unroll
    for (int ma = 0; ma < 2; ma++) {
        const int r0 = q0 + wm*32 + ma*16 + grp;
        #pragma unroll
        for (int na = 0; na < 8; na++) {
            const int v0 = wn*64 + na*8 + qr*2;
            atomicAdd(&out[(size_t)(b*Sc + r0)*OUTC + Dc + v0],     acc[ma][na][0]);
            atomicAdd(&out[(size_t)(b*Sc + r0)*OUTC + Dc + v0 + 1], acc[ma][na][1]);
            atomicAdd(&out[(size_t)(b*Sc + r0 + 8)*OUTC + Dc + v0],     acc[ma][na][2]);
            atomicAdd(&out[(size_t)(b*Sc + r0 + 8)*OUTC + Dc + v0 + 1], acc[ma][na][3]);
        }
    }
}

// ---------------- launch ----------------
extern "C" void kernel_launch(void* const* d_in, const int* in_sizes, int n_in,
                              void* d_out, int out_size) {
    const float* x  = (const float*)d_in[0];
    const float* Wq = (const float*)d_in[1];
    const float* bq = (const float*)d_in[2];
    const float* Wk = (const float*)d_in[3];
    const float* bk = (const float*)d_in[4];
    const float* Wv = (const float*)d_in[5];
    const float* bv = (const float*)d_in[6];
    float* out = (float*)d_out;

    cudaFuncSetAttribute(proj_kernel,   cudaFuncAttributeMaxDynamicSharedMemorySize, PJ_SMEM);
    cudaFuncSetAttribute(scores_kernel, cudaFuncAttributeMaxDynamicSharedMemorySize, SC_SMEM);
    cudaFuncSetAttribute(attn_kernel,   cudaFuncAttributeMaxDynamicSharedMemorySize, AT_SMEM);

    proj_kernel<<<dim3(BSc / 128, 2), 256, PJ_SMEM>>>(x, Wq, bq, Wk, bk, Wv, bv, out);
    scores_kernel<<<dim3(80, Bc), 256, SC_SMEM>>>();
    vprep_kernel<<<dim3(Sc / 64, Bc), 256>>>();
    attn_kernel<<<dim3(80, Bc), 256, AT_SMEM>>>(out);
}